// round 14
// baseline (speedup 1.0000x reference)
#include <cuda_runtime.h>
#include <cuda_bf16.h>
#include <cstdint>
#include <math.h>

#define NQ 65536
#define D  1024
#define NP 512
#define H  128
#define KSPLIT 8

// Scratch (device globals; no allocations allowed)
__device__ float    g_ph_part[KSPLIT * NP * H];  // split-k partials of proto @ W1b
__device__ float    g_proto_h[NP * H];           // reduced [512,128]
__device__ uint32_t g_W1T[H * D];                // W1^T as bf16x2: [n][k/2]
__device__ int      g_amin[NQ];                  // per-query argmin

__device__ __forceinline__ uint32_t packbf(float lo, float hi) {
    uint32_t r;
    asm("cvt.rn.bf16x2.f32 %0, %1, %2;" : "=r"(r) : "f"(hi), "f"(lo));
    return r;
}
__device__ __forceinline__ void mma_bf16(float d[4], const uint32_t a[4],
                                         uint32_t b0, uint32_t b1) {
    asm volatile(
        "mma.sync.aligned.m16n8k16.row.col.f32.bf16.bf16.f32 "
        "{%0,%1,%2,%3}, {%4,%5,%6,%7}, {%8,%9}, {%0,%1,%2,%3};\n"
        : "+f"(d[0]), "+f"(d[1]), "+f"(d[2]), "+f"(d[3])
        : "r"(a[0]), "r"(a[1]), "r"(a[2]), "r"(a[3]), "r"(b0), "r"(b1));
}
__device__ __forceinline__ void cpa16(uint32_t s, const void* g) {
    asm volatile("cp.async.cg.shared.global [%0], [%1], 16;\n" :: "r"(s), "l"(g));
}
__device__ __forceinline__ void cp_commit() {
    asm volatile("cp.async.commit_group;\n" ::: "memory");
}
__device__ __forceinline__ void cp_wait1() {
    asm volatile("cp.async.wait_group 1;" ::: "memory");
}
__device__ __forceinline__ void cp_wait0() {
    asm volatile("cp.async.wait_group 0;" ::: "memory");
}
__device__ __forceinline__ void ldsm4(uint32_t r[4], uint32_t a) {
    asm volatile("ldmatrix.sync.aligned.m8n8.x4.shared.b16 {%0,%1,%2,%3}, [%4];"
                 : "=r"(r[0]), "=r"(r[1]), "=r"(r[2]), "=r"(r[3]) : "r"(a));
}

// ---------------------------------------------------------------------------
// Kernel A: per-query argmin (one warp per query), grid 8192 x 256.
// Blocks 0..255 additionally convert+transpose W1 -> g_W1T (independent work).
// ---------------------------------------------------------------------------
__global__ __launch_bounds__(256)
void argmin_convert_kernel(const float* __restrict__ dist,
                           const float* __restrict__ W1) {
    int q    = blockIdx.x * 8 + (threadIdx.x >> 5);
    int lane = threadIdx.x & 31;
    const float4* row = (const float4*)(dist + (size_t)q * NP);
    float best = 3.402823466e+38f;
    int   bi   = 0;
#pragma unroll
    for (int i = 0; i < 4; i++) {
        int c4 = lane + i * 32;
        float4 v = __ldg(row + c4);
        int c = c4 * 4;
        if (v.x < best) { best = v.x; bi = c; }
        if (v.y < best) { best = v.y; bi = c + 1; }
        if (v.z < best) { best = v.z; bi = c + 2; }
        if (v.w < best) { best = v.w; bi = c + 3; }
    }
#pragma unroll
    for (int off = 16; off; off >>= 1) {
        float ov = __shfl_xor_sync(0xffffffffu, best, off);
        int   oi = __shfl_xor_sync(0xffffffffu, bi, off);
        if (ov < best || (ov == best && oi < bi)) { best = ov; bi = oi; }
    }
    if (lane == 0) g_amin[q] = bi;

    // --- convert part: blocks 0..255 transpose one 32x32 tile of W1 ---
    if (blockIdx.x < 256) {
        __shared__ float t[32][33];
        int kb = (blockIdx.x & 63) * 32, nb = (blockIdx.x >> 6) * 32;
        int r = threadIdx.x >> 5, c = threadIdx.x & 31;
#pragma unroll
        for (int i = 0; i < 4; i++)
            t[r + i * 8][c] = W1[(size_t)(kb + r + i * 8) * H + nb + c];
        __syncthreads();
        int rr = threadIdx.x >> 4, c2 = threadIdx.x & 15;
#pragma unroll
        for (int i = 0; i < 2; i++) {
            int n = rr + i * 16;
            g_W1T[(size_t)(nb + n) * 1024 + kb / 2 + c2] =
                packbf(t[c2 * 2][n], t[c2 * 2 + 1][n]);
        }
    }
}

// ---------------------------------------------------------------------------
// Tile layout (both A and B): bf16 [128 rows][32 k], 64B rows, swizzled:
// addr(row, c16) = (row>>1)*128 + (row&1)*64 + ((c16 ^ ((row>>1)&3))<<4)
// smem: bufA[2] @ 0, bufB[3] @ 16384, aux @ 40960.
// ---------------------------------------------------------------------------
#define ABUF   0
#define BBUF   16384
#define OFF_AUX 40960
#define SMEM_FUSED (OFF_AUX + 512 + 512 + 512 + 1024)
#define SMEM_PROTO OFF_AUX

__device__ __forceinline__ uint32_t tile_addr(int row, int c16) {
    return (uint32_t)((row >> 1) * 128 + (row & 1) * 64 +
                      ((c16 ^ ((row >> 1) & 3)) << 4));
}

__device__ __forceinline__ void tile_mma(uint32_t aB, uint32_t bB,
                                         float acc[2][8][4],
                                         int wm, int wn, int lane) {
    int grp = lane >> 3, l7 = lane & 7;
#pragma unroll
    for (int kc = 0; kc < 2; kc++) {
        uint32_t af[2][4];
#pragma unroll
        for (int mt = 0; mt < 2; mt++) {
            int mrow = wm * 32 + mt * 16 + (grp & 1) * 8 + l7;
            int c16 = kc * 2 + (grp >> 1);
            ldsm4(af[mt], aB + tile_addr(mrow, c16));
        }
#pragma unroll
        for (int ntp = 0; ntp < 4; ntp++) {
            int n = wn * 64 + ntp * 16 + (grp >> 1) * 8 + l7;
            int c16 = kc * 2 + (grp & 1);
            uint32_t b[4];
            ldsm4(b, bB + tile_addr(n, c16));
            mma_bf16(acc[0][ntp * 2],     af[0], b[0], b[1]);
            mma_bf16(acc[1][ntp * 2],     af[1], b[0], b[1]);
            mma_bf16(acc[0][ntp * 2 + 1], af[0], b[2], b[3]);
            mma_bf16(acc[1][ntp * 2 + 1], af[1], b[2], b[3]);
        }
    }
}

// ---- 256-thread loaders ----
__device__ __forceinline__ void load_A_regs(float4 (&fa)[4],
                                            const float* __restrict__ A,
                                            int row0, int kt, int tid) {
#pragma unroll
    for (int i = 0; i < 2; i++) {
        int p = tid + i * 256;
        int r = p >> 2, c = p & 3;
        const float4* src = (const float4*)(A + (size_t)(row0 + r) * D + kt + c * 8);
        fa[2 * i]     = src[0];
        fa[2 * i + 1] = src[1];
    }
}
__device__ __forceinline__ void sts_A(const float4 (&fa)[4], uint32_t aB, int tid) {
#pragma unroll
    for (int i = 0; i < 2; i++) {
        int p = tid + i * 256;
        int r = p >> 2, c = p & 3;
        uint32_t u0 = packbf(fa[2 * i].x, fa[2 * i].y);
        uint32_t u1 = packbf(fa[2 * i].z, fa[2 * i].w);
        uint32_t u2 = packbf(fa[2 * i + 1].x, fa[2 * i + 1].y);
        uint32_t u3 = packbf(fa[2 * i + 1].z, fa[2 * i + 1].w);
        uint32_t ad = aB + tile_addr(r, c);
        asm volatile("st.shared.v4.b32 [%0], {%1,%2,%3,%4};"
                     :: "r"(ad), "r"(u0), "r"(u1), "r"(u2), "r"(u3));
    }
}
__device__ __forceinline__ void load_B_stage(int kt_u32, uint32_t bB, int tid) {
#pragma unroll
    for (int i = 0; i < 2; i++) {
        int p = tid + i * 256;
        int n = p >> 2, c = p & 3;
        cpa16(bB + tile_addr(n, c), g_W1T + (size_t)n * 1024 + kt_u32 + c * 4);
    }
}

// ---------------------------------------------------------------------------
// Kernel 2: proto partials via bf16 mma. grid (4, KSPLIT=8) x 256. K = 128.
// ---------------------------------------------------------------------------
__global__ __launch_bounds__(256, 2)
void proto_mma_kernel(const float* __restrict__ proto) {
    extern __shared__ char smem[];
    uint32_t sb = (uint32_t)__cvta_generic_to_shared(smem);
    int tid = threadIdx.x;
    int mb = blockIdx.x * 128;
    int ks = blockIdx.y;
    int kt0 = ks * 128;                  // proto k base
    int wu0 = 512 + ks * 64;             // u32 col base into g_W1T (W1b half)
    int warp = tid >> 5, lane = tid & 31;
    int wm = warp >> 1, wn = warp & 1;
    int g = lane >> 2, tig = lane & 3;

    float4 fa[4];
    load_A_regs(fa, proto, mb, kt0, tid);
    load_B_stage(wu0,      sb + BBUF,        tid); cp_commit();
    load_B_stage(wu0 + 16, sb + BBUF + 8192, tid); cp_commit();
    sts_A(fa, sb + ABUF, tid);
    load_A_regs(fa, proto, mb, kt0 + 32, tid);

    float acc[2][8][4];
#pragma unroll
    for (int a = 0; a < 2; a++)
#pragma unroll
        for (int b = 0; b < 8; b++)
#pragma unroll
            for (int c = 0; c < 4; c++) acc[a][b][c] = 0.f;

    for (int t = 0; t < 4; t++) {
        if (t < 3) cp_wait1(); else cp_wait0();
        __syncthreads();
        if (t < 3) sts_A(fa, sb + ABUF + ((t + 1) & 1) * 8192, tid);
        if (t < 2) {
            load_A_regs(fa, proto, mb, kt0 + (t + 2) * 32, tid);
            load_B_stage(wu0 + (t + 2) * 16, sb + BBUF + ((t + 2) % 3) * 8192, tid);
            cp_commit();
        }
        tile_mma(sb + ABUF + (t & 1) * 8192, sb + BBUF + (t % 3) * 8192,
                 acc, wm, wn, lane);
    }

    float* dst = g_ph_part + (size_t)ks * NP * H;
#pragma unroll
    for (int mt = 0; mt < 2; mt++)
#pragma unroll
        for (int hh = 0; hh < 2; hh++)
#pragma unroll
            for (int nt = 0; nt < 8; nt++) {
                int row = mb + wm * 32 + mt * 16 + hh * 8 + g;
                int col = wn * 64 + nt * 8 + tig * 2;
                float2 v = make_float2(acc[mt][nt][hh * 2], acc[mt][nt][hh * 2 + 1]);
                *(float2*)(dst + (size_t)row * H + col) = v;
            }
}

// Kernel 3: reduce partials. grid 64 x 256.
__global__ void reduce_ph_kernel() {
    int i = blockIdx.x * 256 + threadIdx.x;
    float4 s = ((const float4*)g_ph_part)[i];
#pragma unroll
    for (int k = 1; k < KSPLIT; k++) {
        float4 v = ((const float4*)g_ph_part)[k * (NP * H / 4) + i];
        s.x += v.x; s.y += v.y; s.z += v.z; s.w += v.w;
    }
    ((float4*)g_proto_h)[i] = s;
}

// ---------------------------------------------------------------------------
// Kernel 4: fused qf @ W1a (bf16 mma + ldmatrix) + MLP epilogue.
// Argmin comes precomputed from g_amin. Mainloop = pure GEMM pipeline.
// ---------------------------------------------------------------------------
__global__ __launch_bounds__(256, 2)
void fused_kernel(const float* __restrict__ qf, const float* __restrict__ b1,
                  const float* __restrict__ W2, const float* __restrict__ b2,
                  float* __restrict__ out) {
    extern __shared__ char smem[];
    uint32_t sb = (uint32_t)__cvta_generic_to_shared(smem);
    float* b1s    = (float*)(smem + OFF_AUX);
    float* w2s    = b1s + 128;
    int*   amin_s = (int*)(w2s + 128);
    float* psum   = (float*)(amin_s + 128);

    int tid = threadIdx.x;
    int mblock = blockIdx.x * 128;
    int warp = tid >> 5, lane = tid & 31;
    int wm = warp >> 1, wn = warp & 1;
    int g = lane >> 2, tig = lane & 3;

    float4 fa[4];
    load_A_regs(fa, qf, mblock, 0, tid);
    load_B_stage(0,  sb + BBUF,        tid); cp_commit();
    load_B_stage(16, sb + BBUF + 8192, tid); cp_commit();
    sts_A(fa, sb + ABUF, tid);
    load_A_regs(fa, qf, mblock, 32, tid);

    if (tid < 128) {
        b1s[tid] = b1[tid];
        w2s[tid] = W2[tid];
        amin_s[tid] = __ldg(g_amin + mblock + tid);
    }

    float acc[2][8][4];
#pragma unroll
    for (int a = 0; a < 2; a++)
#pragma unroll
        for (int b = 0; b < 8; b++)
#pragma unroll
            for (int c = 0; c < 4; c++) acc[a][b][c] = 0.f;

    for (int t = 0; t < 32; t++) {
        if (t < 31) cp_wait1(); else cp_wait0();
        __syncthreads();
        if (t < 31) sts_A(fa, sb + ABUF + ((t + 1) & 1) * 8192, tid);
        if (t < 30) {
            load_A_regs(fa, qf, mblock, (t + 2) * 32, tid);
            load_B_stage((t + 2) * 16, sb + BBUF + ((t + 2) % 3) * 8192, tid);
            cp_commit();
        }
        tile_mma(sb + ABUF + (t & 1) * 8192, sb + BBUF + (t % 3) * 8192,
                 acc, wm, wn, lane);
    }
    __syncthreads();   // make amin_s/b1s visible + all MMA consumed

    // Epilogue
    float b2v = __ldg(b2);
#pragma unroll
    for (int mt = 0; mt < 2; mt++) {
#pragma unroll
        for (int hh = 0; hh < 2; hh++) {
            int rloc = wm * 32 + mt * 16 + hh * 8 + g;
            const float* ph = g_proto_h + (size_t)amin_s[rloc] * H;
            float p = 0.f;
#pragma unroll
            for (int nt = 0; nt < 8; nt++) {
#pragma unroll
                for (int j = 0; j < 2; j++) {
                    int n = wn * 64 + nt * 8 + tig * 2 + j;
                    float v = acc[mt][nt][hh * 2 + j] + ph[n] + b1s[n];
                    p += fmaxf(v, 0.f) * w2s[n];
                }
            }
            p += __shfl_xor_sync(0xffffffffu, p, 1);
            p += __shfl_xor_sync(0xffffffffu, p, 2);
            if (tig == 0) psum[rloc * 2 + wn] = p;
        }
    }
    __syncthreads();
    if (tid < 128) {
        float logit = psum[tid * 2] + psum[tid * 2 + 1] + b2v;
        out[mblock + tid] = 1.f / (1.f + __expf(-logit));
    }
}

// ---------------------------------------------------------------------------
extern "C" void kernel_launch(void* const* d_in, const int* in_sizes, int n_in,
                              void* d_out, int out_size) {
    const float* qf    = (const float*)d_in[0];
    const float* proto = (const float*)d_in[1];
    const float* dist  = (const float*)d_in[2];
    const float* W1    = (const float*)d_in[3];
    const float* b1    = (const float*)d_in[4];
    const float* W2    = (const float*)d_in[5];
    const float* b2    = (const float*)d_in[6];
    float* out = (float*)d_out;

    static int attr_set = 0;
    if (!attr_set) {
        cudaFuncSetAttribute(fused_kernel,
                             cudaFuncAttributeMaxDynamicSharedMemorySize, SMEM_FUSED);
        cudaFuncSetAttribute(proto_mma_kernel,
                             cudaFuncAttributeMaxDynamicSharedMemorySize, SMEM_PROTO);
        attr_set = 1;
    }

    argmin_convert_kernel<<<NQ / 8, 256>>>(dist, W1);
    proto_mma_kernel<<<dim3(NP / 128, KSPLIT), 256, SMEM_PROTO>>>(proto);
    reduce_ph_kernel<<<NP * H / 4 / 256, 256>>>();
    fused_kernel<<<NQ / 128, 256, SMEM_FUSED>>>(qf, b1, W2, b2, out);
}

// round 16
// speedup vs baseline: 1.0628x; 1.0628x over previous
#include <cuda_runtime.h>
#include <cuda_bf16.h>
#include <cstdint>
#include <math.h>

#define NQ 65536
#define D  1024
#define NP 512
#define H  128
#define KSPLIT 8

// Scratch (device globals; no allocations allowed)
__device__ float    g_ph_part[KSPLIT * NP * H];  // split-k partials of proto @ W1b
__device__ float    g_proto_h[NP * H];           // reduced [512,128]
__device__ uint32_t g_W1T[H * D];                // W1^T as bf16x2: [n][k/2]

__device__ __forceinline__ uint32_t packbf(float lo, float hi) {
    uint32_t r;
    asm("cvt.rn.bf16x2.f32 %0, %1, %2;" : "=r"(r) : "f"(hi), "f"(lo));
    return r;
}
__device__ __forceinline__ void mma_bf16(float d[4], const uint32_t a[4],
                                         uint32_t b0, uint32_t b1) {
    asm volatile(
        "mma.sync.aligned.m16n8k16.row.col.f32.bf16.bf16.f32 "
        "{%0,%1,%2,%3}, {%4,%5,%6,%7}, {%8,%9}, {%0,%1,%2,%3};\n"
        : "+f"(d[0]), "+f"(d[1]), "+f"(d[2]), "+f"(d[3])
        : "r"(a[0]), "r"(a[1]), "r"(a[2]), "r"(a[3]), "r"(b0), "r"(b1));
}
__device__ __forceinline__ void cpa16(uint32_t s, const void* g) {
    asm volatile("cp.async.cg.shared.global [%0], [%1], 16;\n" :: "r"(s), "l"(g));
}
__device__ __forceinline__ void cp_commit() {
    asm volatile("cp.async.commit_group;\n" ::: "memory");
}
__device__ __forceinline__ void cp_wait1() {
    asm volatile("cp.async.wait_group 1;" ::: "memory");
}
__device__ __forceinline__ void cp_wait0() {
    asm volatile("cp.async.wait_group 0;" ::: "memory");
}
__device__ __forceinline__ void ldsm4(uint32_t r[4], uint32_t a) {
    asm volatile("ldmatrix.sync.aligned.m8n8.x4.shared.b16 {%0,%1,%2,%3}, [%4];"
                 : "=r"(r[0]), "=r"(r[1]), "=r"(r[2]), "=r"(r[3]) : "r"(a));
}
__device__ __forceinline__ uint32_t redux_min_u32(uint32_t v) {
    uint32_t r;
    asm volatile("redux.sync.min.u32 %0, %1, 0xffffffff;" : "=r"(r) : "r"(v));
    return r;
}

// ---------------------------------------------------------------------------
// Kernel 1: convert+transpose full W1 [2048][128] f32 -> g_W1T [128][2048] bf16
// ---------------------------------------------------------------------------
__global__ __launch_bounds__(256)
void convert_w1t_kernel(const float* __restrict__ W1) {
    __shared__ float t[32][33];
    int kb = blockIdx.x * 32, nb = blockIdx.y * 32;
    int r = threadIdx.x >> 5, c = threadIdx.x & 31;
#pragma unroll
    for (int i = 0; i < 4; i++)
        t[r + i * 8][c] = W1[(size_t)(kb + r + i * 8) * H + nb + c];
    __syncthreads();
    int rr = threadIdx.x >> 4, c2 = threadIdx.x & 15;
#pragma unroll
    for (int i = 0; i < 2; i++) {
        int n = rr + i * 16;
        g_W1T[(size_t)(nb + n) * 1024 + kb / 2 + c2] =
            packbf(t[c2 * 2][n], t[c2 * 2 + 1][n]);
    }
}

// ---------------------------------------------------------------------------
// Tile layout (both A and B): bf16 [128 rows][32 k], 64B rows, swizzled:
// addr(row, c16) = (row>>1)*128 + (row&1)*64 + ((c16 ^ ((row>>1)&3))<<4)
// smem: bufA[2] @ 0, bufB[3] @ 16384, aux @ 40960.
// ---------------------------------------------------------------------------
#define ABUF   0
#define BBUF   16384
#define OFF_AUX 40960
#define SMEM_FUSED (OFF_AUX + 512 + 512 + 512 + 1024)
#define SMEM_PROTO OFF_AUX

__device__ __forceinline__ uint32_t tile_addr(int row, int c16) {
    return (uint32_t)((row >> 1) * 128 + (row & 1) * 64 +
                      ((c16 ^ ((row >> 1) & 3)) << 4));
}

__device__ __forceinline__ void tile_mma(uint32_t aB, uint32_t bB,
                                         float acc[2][8][4],
                                         int wm, int wn, int lane) {
    int grp = lane >> 3, l7 = lane & 7;
#pragma unroll
    for (int kc = 0; kc < 2; kc++) {
        uint32_t af[2][4];
#pragma unroll
        for (int mt = 0; mt < 2; mt++) {
            int mrow = wm * 32 + mt * 16 + (grp & 1) * 8 + l7;
            int c16 = kc * 2 + (grp >> 1);
            ldsm4(af[mt], aB + tile_addr(mrow, c16));
        }
#pragma unroll
        for (int ntp = 0; ntp < 4; ntp++) {
            int n = wn * 64 + ntp * 16 + (grp >> 1) * 8 + l7;
            int c16 = kc * 2 + (grp & 1);
            uint32_t b[4];
            ldsm4(b, bB + tile_addr(n, c16));
            mma_bf16(acc[0][ntp * 2],     af[0], b[0], b[1]);
            mma_bf16(acc[1][ntp * 2],     af[1], b[0], b[1]);
            mma_bf16(acc[0][ntp * 2 + 1], af[0], b[2], b[3]);
            mma_bf16(acc[1][ntp * 2 + 1], af[1], b[2], b[3]);
        }
    }
}

// ---- 256-thread loaders ----
__device__ __forceinline__ void load_A_regs(float4 (&fa)[4],
                                            const float* __restrict__ A,
                                            int row0, int kt, int tid) {
#pragma unroll
    for (int i = 0; i < 2; i++) {
        int p = tid + i * 256;
        int r = p >> 2, c = p & 3;
        const float4* src = (const float4*)(A + (size_t)(row0 + r) * D + kt + c * 8);
        fa[2 * i]     = src[0];
        fa[2 * i + 1] = src[1];
    }
}
__device__ __forceinline__ void sts_A(const float4 (&fa)[4], uint32_t aB, int tid) {
#pragma unroll
    for (int i = 0; i < 2; i++) {
        int p = tid + i * 256;
        int r = p >> 2, c = p & 3;
        uint32_t u0 = packbf(fa[2 * i].x, fa[2 * i].y);
        uint32_t u1 = packbf(fa[2 * i].z, fa[2 * i].w);
        uint32_t u2 = packbf(fa[2 * i + 1].x, fa[2 * i + 1].y);
        uint32_t u3 = packbf(fa[2 * i + 1].z, fa[2 * i + 1].w);
        uint32_t ad = aB + tile_addr(r, c);
        asm volatile("st.shared.v4.b32 [%0], {%1,%2,%3,%4};"
                     :: "r"(ad), "r"(u0), "r"(u1), "r"(u2), "r"(u3));
    }
}
__device__ __forceinline__ void load_B_stage(int kt_u32, uint32_t bB, int tid) {
#pragma unroll
    for (int i = 0; i < 2; i++) {
        int p = tid + i * 256;
        int n = p >> 2, c = p & 3;
        cpa16(bB + tile_addr(n, c), g_W1T + (size_t)n * 1024 + kt_u32 + c * 4);
    }
}

// ---------------------------------------------------------------------------
// Kernel 2: proto partials via bf16 mma. grid (4, KSPLIT=8) x 256. K = 128.
// ---------------------------------------------------------------------------
__global__ __launch_bounds__(256, 2)
void proto_mma_kernel(const float* __restrict__ proto) {
    extern __shared__ char smem[];
    uint32_t sb = (uint32_t)__cvta_generic_to_shared(smem);
    int tid = threadIdx.x;
    int mb = blockIdx.x * 128;
    int ks = blockIdx.y;
    int kt0 = ks * 128;                  // proto k base
    int wu0 = 512 + ks * 64;             // u32 col base into g_W1T (W1b half)
    int warp = tid >> 5, lane = tid & 31;
    int wm = warp >> 1, wn = warp & 1;
    int g = lane >> 2, tig = lane & 3;

    float4 fa[4];
    load_A_regs(fa, proto, mb, kt0, tid);
    load_B_stage(wu0,      sb + BBUF,        tid); cp_commit();
    load_B_stage(wu0 + 16, sb + BBUF + 8192, tid); cp_commit();
    sts_A(fa, sb + ABUF, tid);
    load_A_regs(fa, proto, mb, kt0 + 32, tid);

    float acc[2][8][4];
#pragma unroll
    for (int a = 0; a < 2; a++)
#pragma unroll
        for (int b = 0; b < 8; b++)
#pragma unroll
            for (int c = 0; c < 4; c++) acc[a][b][c] = 0.f;

    for (int t = 0; t < 4; t++) {
        if (t < 3) cp_wait1(); else cp_wait0();
        __syncthreads();
        if (t < 3) sts_A(fa, sb + ABUF + ((t + 1) & 1) * 8192, tid);
        if (t < 2) {
            load_A_regs(fa, proto, mb, kt0 + (t + 2) * 32, tid);
            load_B_stage(wu0 + (t + 2) * 16, sb + BBUF + ((t + 2) % 3) * 8192, tid);
            cp_commit();
        }
        tile_mma(sb + ABUF + (t & 1) * 8192, sb + BBUF + (t % 3) * 8192,
                 acc, wm, wn, lane);
    }

    float* dst = g_ph_part + (size_t)ks * NP * H;
#pragma unroll
    for (int mt = 0; mt < 2; mt++)
#pragma unroll
        for (int hh = 0; hh < 2; hh++)
#pragma unroll
            for (int nt = 0; nt < 8; nt++) {
                int row = mb + wm * 32 + mt * 16 + hh * 8 + g;
                int col = wn * 64 + nt * 8 + tig * 2;
                float2 v = make_float2(acc[mt][nt][hh * 2], acc[mt][nt][hh * 2 + 1]);
                *(float2*)(dst + (size_t)row * H + col) = v;
            }
}

// Kernel 3: reduce partials. grid 64 x 256.
__global__ void reduce_ph_kernel() {
    int i = blockIdx.x * 256 + threadIdx.x;
    float4 s = ((const float4*)g_ph_part)[i];
#pragma unroll
    for (int k = 1; k < KSPLIT; k++) {
        float4 v = ((const float4*)g_ph_part)[k * (NP * H / 4) + i];
        s.x += v.x; s.y += v.y; s.z += v.z; s.w += v.w;
    }
    ((float4*)g_proto_h)[i] = s;
}

// ---------------------------------------------------------------------------
// Kernel 4: fused qf @ W1a (bf16 mma + ldmatrix), argmin folded (half-row per
// iteration, redux.sync reduction), MLP epilogue.
// ---------------------------------------------------------------------------
__global__ __launch_bounds__(256, 2)
void fused_kernel(const float* __restrict__ qf, const float* __restrict__ b1,
                  const float* __restrict__ W2, const float* __restrict__ b2,
                  const float* __restrict__ dist, float* __restrict__ out) {
    extern __shared__ char smem[];
    uint32_t sb = (uint32_t)__cvta_generic_to_shared(smem);
    float* b1s    = (float*)(smem + OFF_AUX);
    float* w2s    = b1s + 128;
    int*   amin_s = (int*)(w2s + 128);
    float* psum   = (float*)(amin_s + 128);

    int tid = threadIdx.x;
    int mblock = blockIdx.x * 128;
    int warp = tid >> 5, lane = tid & 31;
    int wm = warp >> 1, wn = warp & 1;
    int g = lane >> 2, tig = lane & 3;

    float4 fa[4];
    load_A_regs(fa, qf, mblock, 0, tid);
    load_B_stage(0,  sb + BBUF,        tid); cp_commit();
    load_B_stage(16, sb + BBUF + 8192, tid); cp_commit();
    sts_A(fa, sb + ABUF, tid);
    load_A_regs(fa, qf, mblock, 32, tid);

    if (tid < 128) { b1s[tid] = b1[tid]; w2s[tid] = W2[tid]; }

    // argmin: warp owns rows [warp*16, warp*16+16); one half-row per iter.
    const float* dbase = dist + (size_t)(mblock + warp * 16) * NP;
    float4 av0, av1;
    {
        const float4* rp = (const float4*)dbase;
        av0 = rp[lane]; av1 = rp[lane + 32];
    }
    float bestc = 0.f; int bic = 0;

    float acc[2][8][4];
#pragma unroll
    for (int a = 0; a < 2; a++)
#pragma unroll
        for (int b = 0; b < 8; b++)
#pragma unroll
            for (int c = 0; c < 4; c++) acc[a][b][c] = 0.f;

    for (int t = 0; t < 32; t++) {
        if (t < 31) cp_wait1(); else cp_wait0();
        __syncthreads();
        if (t < 31) sts_A(fa, sb + ABUF + ((t + 1) & 1) * 8192, tid);
        if (t < 30) {
            load_A_regs(fa, qf, mblock, (t + 2) * 32, tid);
            load_B_stage((t + 2) * 16, sb + BBUF + ((t + 2) % 3) * 8192, tid);
            cp_commit();
        }
        {   // argmin half-row t
            int row = t >> 1, part = t & 1;
            int cb = part * 256 + lane * 4;
            float best = av0.x; int bi = cb;
            if (av0.y < best) { best = av0.y; bi = cb + 1; }
            if (av0.z < best) { best = av0.z; bi = cb + 2; }
            if (av0.w < best) { best = av0.w; bi = cb + 3; }
            if (av1.x < best) { best = av1.x; bi = cb + 128; }
            if (av1.y < best) { best = av1.y; bi = cb + 129; }
            if (av1.z < best) { best = av1.z; bi = cb + 130; }
            if (av1.w < best) { best = av1.w; bi = cb + 131; }
            if (part == 0) { bestc = best; bic = bi; }
            else {
                // merge part0 (all its indices are smaller -> <= keeps part0 on tie)
                if (bestc <= best) { best = bestc; bi = bic; }
                // exact warp argmin: distances >= 0 so fp32 bits are order-
                // isomorphic to u32; second redux picks lowest index on ties.
                uint32_t fb = __float_as_uint(best);
                uint32_t mv = redux_min_u32(fb);
                uint32_t cand = (fb == mv) ? (uint32_t)bi : 0xFFFFFFFFu;
                uint32_t mi = redux_min_u32(cand);
                if (lane == 0) amin_s[warp * 16 + row] = (int)mi;
            }
            if (t + 1 < 32) {   // prefetch next half-row
                int nr = (t + 1) >> 1, np = (t + 1) & 1;
                const float4* rp = (const float4*)(dbase + (size_t)nr * NP + np * 256);
                av0 = rp[lane]; av1 = rp[lane + 32];
            }
        }
        tile_mma(sb + ABUF + (t & 1) * 8192, sb + BBUF + (t % 3) * 8192,
                 acc, wm, wn, lane);
    }
    __syncthreads();   // amin_s written up to t=31; make visible cross-warp

    // Epilogue
    float b2v = __ldg(b2);
#pragma unroll
    for (int mt = 0; mt < 2; mt++) {
#pragma unroll
        for (int hh = 0; hh < 2; hh++) {
            int rloc = wm * 32 + mt * 16 + hh * 8 + g;
            const float* ph = g_proto_h + (size_t)amin_s[rloc] * H;
            float p = 0.f;
#pragma unroll
            for (int nt = 0; nt < 8; nt++) {
#pragma unroll
                for (int j = 0; j < 2; j++) {
                    int n = wn * 64 + nt * 8 + tig * 2 + j;
                    float v = acc[mt][nt][hh * 2 + j] + ph[n] + b1s[n];
                    p += fmaxf(v, 0.f) * w2s[n];
                }
            }
            p += __shfl_xor_sync(0xffffffffu, p, 1);
            p += __shfl_xor_sync(0xffffffffu, p, 2);
            if (tig == 0) psum[rloc * 2 + wn] = p;
        }
    }
    __syncthreads();
    if (tid < 128) {
        float logit = psum[tid * 2] + psum[tid * 2 + 1] + b2v;
        out[mblock + tid] = 1.f / (1.f + __expf(-logit));
    }
}

// ---------------------------------------------------------------------------
extern "C" void kernel_launch(void* const* d_in, const int* in_sizes, int n_in,
                              void* d_out, int out_size) {
    const float* qf    = (const float*)d_in[0];
    const float* proto = (const float*)d_in[1];
    const float* dist  = (const float*)d_in[2];
    const float* W1    = (const float*)d_in[3];
    const float* b1    = (const float*)d_in[4];
    const float* W2    = (const float*)d_in[5];
    const float* b2    = (const float*)d_in[6];
    float* out = (float*)d_out;

    static int attr_set = 0;
    if (!attr_set) {
        cudaFuncSetAttribute(fused_kernel,
                             cudaFuncAttributeMaxDynamicSharedMemorySize, SMEM_FUSED);
        cudaFuncSetAttribute(proto_mma_kernel,
                             cudaFuncAttributeMaxDynamicSharedMemorySize, SMEM_PROTO);
        attr_set = 1;
    }

    convert_w1t_kernel<<<dim3(2 * D / 32, H / 32), 256>>>(W1);
    proto_mma_kernel<<<dim3(NP / 128, KSPLIT), 256, SMEM_PROTO>>>(proto);
    reduce_ph_kernel<<<NP * H / 4 / 256, 256>>>();
    fused_kernel<<<NQ / 128, 256, SMEM_FUSED>>>(qf, b1, W2, b2, dist, out);
}